// round 3
// baseline (speedup 1.0000x reference)
#include <cuda_runtime.h>
#include <stdint.h>
#include <math.h>

#define BB 16
#define CC 3
#define HH 224
#define WWIDTH 224
#define HW (HH*WWIDTH)        // 50176
#define EMBN 16
#define NSEG 196
#define MCN 16
#define NTOT (BB*NSEG*MCN)    // 50176

#define SZ_MASK (BB*CC*HW*MCN)   // 38535168
#define OFF_GP  (SZ_MASK)
#define SZ_GP   (BB*NSEG)
#define OFF_PP  (OFF_GP + SZ_GP)
#define SZ_PP   (BB*HW)
#define OFF_SIG (OFF_PP + SZ_PP)

#define LDA 197

// -------------------- device scratch (no allocations allowed) --------------------
__device__ float g_sums[BB*NSEG*17];
__device__ float g_mu[BB*NSEG];
__device__ float g_gemb[BB*NSEG*16];
__device__ float g_L[BB*NSEG*NSEG];
__device__ float g_eps[NTOT];
__device__ float g_logi[NTOT];
__device__ float g_hard[NTOT];

// -------------------- threefry2x32 (20 rounds), host+device --------------------
__host__ __device__ inline void tf2x32(uint32_t k0, uint32_t k1,
                                       uint32_t x0, uint32_t x1,
                                       uint32_t& o0, uint32_t& o1) {
    uint32_t ks2 = k0 ^ k1 ^ 0x1BD11BDAu;
    x0 += k0; x1 += k1;
#define TF_RND(r) { x0 += x1; x1 = (x1 << (r)) | (x1 >> (32 - (r))); x1 ^= x0; }
    TF_RND(13) TF_RND(15) TF_RND(26) TF_RND(6)
    x0 += k1;  x1 += ks2 + 1u;
    TF_RND(17) TF_RND(29) TF_RND(16) TF_RND(24)
    x0 += ks2; x1 += k0 + 2u;
    TF_RND(13) TF_RND(15) TF_RND(26) TF_RND(6)
    x0 += k0;  x1 += k1 + 3u;
    TF_RND(17) TF_RND(29) TF_RND(16) TF_RND(24)
    x0 += k1;  x1 += ks2 + 4u;
    TF_RND(13) TF_RND(15) TF_RND(26) TF_RND(6)
    x0 += ks2; x1 += k0 + 5u;
#undef TF_RND
    o0 = x0; o1 = x1;
}

// XLA ErfInv32 (Giles polynomial), matches lax.erf_inv lowering
__device__ __forceinline__ float erfinv_xla(float x) {
    float w = -log1pf(-x * x);
    float p;
    if (w < 5.0f) {
        w = w - 2.5f;
        p =               2.81022636e-08f;
        p = fmaf(p, w,    3.43273939e-07f);
        p = fmaf(p, w,   -3.5233877e-06f);
        p = fmaf(p, w,   -4.39150654e-06f);
        p = fmaf(p, w,    0.00021858087f);
        p = fmaf(p, w,   -0.00125372503f);
        p = fmaf(p, w,   -0.00417768164f);
        p = fmaf(p, w,    0.246640727f);
        p = fmaf(p, w,    1.50140941f);
    } else {
        w = sqrtf(w) - 3.0f;
        p =              -0.000200214257f;
        p = fmaf(p, w,    0.000100950558f);
        p = fmaf(p, w,    0.00134934322f);
        p = fmaf(p, w,   -0.00367342844f);
        p = fmaf(p, w,    0.00573950773f);
        p = fmaf(p, w,   -0.0076224613f);
        p = fmaf(p, w,    0.00943887047f);
        p = fmaf(p, w,    1.00167406f);
        p = fmaf(p, w,    2.83297682f);
    }
    return p * x;
}

// -------------------- kernel 1: 1x1 conv + pixel_probs + segment sums --------------------
__global__ void k_emb_sums(const float* __restrict__ x, const int* __restrict__ groups,
                           const float* __restrict__ Wc, const float* __restrict__ bc,
                           float* __restrict__ out_pp) {
    __shared__ float sW[EMBN*CC];
    __shared__ float sB[EMBN];
    __shared__ float acc[NSEG*17];
    const int tid = threadIdx.x;
    const int b   = blockIdx.y;
    if (tid < EMBN*CC) sW[tid] = Wc[tid];
    if (tid < EMBN)    sB[tid] = bc[tid];
    for (int i = tid; i < NSEG*17; i += blockDim.x) acc[i] = 0.0f;
    __syncthreads();

    const int chunk = HW / gridDim.x;
    const int p0 = blockIdx.x * chunk;
    const float* xb = x + (size_t)b * CC * HW;
    for (int p = p0 + tid; p < p0 + chunk; p += blockDim.x) {
        float x0 = xb[p], x1 = xb[HW + p], x2 = xb[2*HW + p];
        int g = groups[b*HW + p];
        float* a = acc + g * 17;
#pragma unroll
        for (int e = 0; e < EMBN; ++e) {
            float s = fmaf(x2, sW[e*3+2], fmaf(x1, sW[e*3+1], x0 * sW[e*3]));
            float v = s + sB[e];
            if (e == 0) out_pp[b*HW + p] = 1.0f / (1.0f + expf(-v));
            atomicAdd(&a[e], v);
        }
        atomicAdd(&a[16], 1.0f);
    }
    __syncthreads();
    float* gs = g_sums + b * NSEG * 17;
    for (int i = tid; i < NSEG*17; i += blockDim.x) atomicAdd(&gs[i], acc[i]);
}

// -------------------- kernel 2: means, mu, gemb, group_probs --------------------
__global__ void k_means(float* __restrict__ out_gp) {
    int t = blockIdx.x * blockDim.x + threadIdx.x;
    if (t >= BB*NSEG) return;
    const float* s = g_sums + t * 17;
    float cm = fmaxf(s[16], 1.0f);
    float a0 = s[0] / cm;
    g_mu[t] = a0;
    out_gp[t] = 1.0f / (1.0f + expf(-a0));
    float* ge = g_gemb + t * 16;
#pragma unroll
    for (int e = 1; e < 16; ++e) ge[e-1] = s[e] / cm;
    ge[15] = 0.0f;
}

// -------------------- kernel 3: sigma = gemb gemb^T + jitter*I --------------------
__global__ void k_sigma(float* __restrict__ out_sig) {
    const int sRow = blockIdx.x, b = blockIdx.y;
    __shared__ float gs[16];
    int t = threadIdx.x;
    if (t < 16) gs[t] = g_gemb[(b*NSEG + sRow)*16 + t];
    __syncthreads();
    if (t >= NSEG) return;
    const float4* gt = (const float4*)(g_gemb + (size_t)(b*NSEG + t)*16);
    float4 a0 = gt[0], a1 = gt[1], a2 = gt[2], a3 = gt[3];
    float d = gs[0]*a0.x;
    d = fmaf(gs[1],  a0.y, d); d = fmaf(gs[2],  a0.z, d); d = fmaf(gs[3],  a0.w, d);
    d = fmaf(gs[4],  a1.x, d); d = fmaf(gs[5],  a1.y, d); d = fmaf(gs[6],  a1.z, d);
    d = fmaf(gs[7],  a1.w, d); d = fmaf(gs[8],  a2.x, d); d = fmaf(gs[9],  a2.y, d);
    d = fmaf(gs[10], a2.z, d); d = fmaf(gs[11], a2.w, d); d = fmaf(gs[12], a3.x, d);
    d = fmaf(gs[13], a3.y, d); d = fmaf(gs[14], a3.z, d);
    if (t == sRow) d += 0.001f;
    out_sig[(size_t)(b*NSEG + sRow)*NSEG + t] = d;
}

// -------------------- kernel 4: blocked Cholesky, one CTA per batch --------------------
__global__ void k_chol(const float* __restrict__ sig) {
    extern __shared__ float A[];  // LDA * 200 floats
    const int b = blockIdx.x, tid = threadIdx.x, nt = blockDim.x;
    const float* S = sig + (size_t)b * NSEG * NSEG;
    for (int idx = tid; idx < NSEG*NSEG; idx += nt) {
        int i = idx / NSEG, j = idx - i*NSEG;
        if (j <= i) A[i*LDA + j] = S[idx];
    }
    __syncthreads();
    const int BS = 14;
    for (int kb = 0; kb < NSEG; kb += BS) {
        const int jend = kb + BS;
        // panel factorization (columns kb..jend-1, all rows)
        for (int k = kb; k < jend; ++k) {
            float akk = A[k*LDA + k];
            float inv = 1.0f / sqrtf(akk);
            for (int i = k + 1 + tid; i < NSEG; i += nt) A[i*LDA + k] *= inv;
            __syncthreads();
            for (int j = k + 1; j < jend; ++j) {
                float ljk = A[j*LDA + k];
                for (int i = j + tid; i < NSEG; i += nt)
                    A[i*LDA + j] = fmaf(-A[i*LDA + k], ljk, A[i*LDA + j]);
            }
            __syncthreads();
        }
        // trailing SYRK update: C -= P P^T over rows/cols >= jend, 4x4 register tiles
        const int t0 = jend;
        const int m = NSEG - t0;
        if (m > 0) {
            const int nt4 = (m + 3) >> 2;
            const int ntiles = nt4 * (nt4 + 1) / 2;
            for (int tt = tid; tt < ntiles; tt += nt) {
                int ti = (int)((sqrtf(8.0f*tt + 1.0f) - 1.0f) * 0.5f);
                while ((ti + 1)*(ti + 2)/2 <= tt) ++ti;
                while (ti*(ti + 1)/2 > tt) --ti;
                int tj = tt - ti*(ti + 1)/2;
                int i0 = t0 + ti*4, j0 = t0 + tj*4;
                float c00=0,c01=0,c02=0,c03=0, c10=0,c11=0,c12=0,c13=0;
                float c20=0,c21=0,c22=0,c23=0, c30=0,c31=0,c32=0,c33=0;
                for (int c = kb; c < jend; ++c) {
                    float pi0 = A[(i0+0)*LDA + c], pi1 = A[(i0+1)*LDA + c];
                    float pi2 = A[(i0+2)*LDA + c], pi3 = A[(i0+3)*LDA + c];
                    float pj0 = A[(j0+0)*LDA + c], pj1 = A[(j0+1)*LDA + c];
                    float pj2 = A[(j0+2)*LDA + c], pj3 = A[(j0+3)*LDA + c];
                    c00 = fmaf(pi0, pj0, c00); c01 = fmaf(pi0, pj1, c01);
                    c02 = fmaf(pi0, pj2, c02); c03 = fmaf(pi0, pj3, c03);
                    c10 = fmaf(pi1, pj0, c10); c11 = fmaf(pi1, pj1, c11);
                    c12 = fmaf(pi1, pj2, c12); c13 = fmaf(pi1, pj3, c13);
                    c20 = fmaf(pi2, pj0, c20); c21 = fmaf(pi2, pj1, c21);
                    c22 = fmaf(pi2, pj2, c22); c23 = fmaf(pi2, pj3, c23);
                    c30 = fmaf(pi3, pj0, c30); c31 = fmaf(pi3, pj1, c31);
                    c32 = fmaf(pi3, pj2, c32); c33 = fmaf(pi3, pj3, c33);
                }
                float cc[4][4] = {{c00,c01,c02,c03},{c10,c11,c12,c13},
                                  {c20,c21,c22,c23},{c30,c31,c32,c33}};
#pragma unroll
                for (int ii = 0; ii < 4; ++ii)
#pragma unroll
                    for (int jj = 0; jj < 4; ++jj) {
                        int i = i0 + ii, j = j0 + jj;
                        if (i < NSEG && j <= i) A[i*LDA + j] -= cc[ii][jj];
                    }
            }
        }
        __syncthreads();
    }
    for (int idx = tid; idx < NSEG*NSEG; idx += nt) {
        int i = idx / NSEG, j = idx - i*NSEG;
        if (j < i)       g_L[(size_t)b*NSEG*NSEG + idx] = A[i*LDA + j];
        else if (j == i) g_L[(size_t)b*NSEG*NSEG + idx] = sqrtf(A[i*LDA + j]);
    }
}

// -------------------- kernel 5: threefry RNG -> eps, logistic --------------------
// jax partitionable random_bits (32-bit): bits[i] = o0 ^ o1 of threefry(key, hi=0, lo=i)
__global__ void k_rng(uint32_t g0, uint32_t g1, uint32_t u0, uint32_t u1) {
    int i = blockIdx.x * blockDim.x + threadIdx.x;
    if (i >= NTOT) return;
    uint32_t a0, a1;
    tf2x32(g0, g1, 0u, (uint32_t)i, a0, a1);
    {
        uint32_t bits = a0 ^ a1;
        float f  = __uint_as_float((bits >> 9) | 0x3f800000u) - 1.0f;
        const float lo = __uint_as_float(0xBF7FFFFFu);   // nextafter(-1, 0)
        const float d  = __fadd_rn(1.0f, -lo);           // = 2.0f in f32
        float u  = fmaxf(lo, __fadd_rn(__fmul_rn(f, d), lo));
        g_eps[i] = __uint_as_float(0x3FB504F3u) * erfinv_xla(u);  // sqrt(2)_f32 * erfinv
    }
    tf2x32(u0, u1, 0u, (uint32_t)i, a0, a1);
    {
        uint32_t bits = a0 ^ a1;
        float f  = __uint_as_float((bits >> 9) | 0x3f800000u) - 1.0f;
        const float lo = 1e-6f;
        const float hi = (float)(1.0 - 1e-6);
        const float d  = __fadd_rn(hi, -lo);
        float u  = fmaxf(lo, __fadd_rn(__fmul_rn(f, d), lo));
        g_logi[i] = logf(u) - log1pf(-u);
    }
}

// -------------------- kernel 6: logits = mu + L@eps + logistic -> hard --------------------
__global__ void k_logits() {
    __shared__ float se[NSEG*MCN];  // eps for this batch
    const int b = blockIdx.y;
    const int tid = threadIdx.x;
    for (int i = tid; i < NSEG*MCN; i += 256) se[i] = g_eps[b*NSEG*MCN + i];
    __syncthreads();
    const int m = tid & 15, sl = tid >> 4;
    const int s = blockIdx.x * 16 + sl;
    if (s >= NSEG) return;
    const float* Lr = g_L + ((size_t)b*NSEG + s) * NSEG;
    float acc = g_mu[b*NSEG + s];
    for (int t = 0; t <= s; ++t) acc = fmaf(Lr[t], se[t*MCN + m], acc);
    float z = acc + g_logi[(b*NSEG + s)*MCN + m];
    float r = 1.0f / (1.0f + expf(-z));
    g_hard[(b*NSEG + s)*MCN + m] = (r > 0.5f) ? 1.0f : 0.0f;
}

// -------------------- kernel 7: gather mask (HBM-bound) --------------------
__global__ void k_mask(const int* __restrict__ groups, float* __restrict__ mask) {
    const int idx = blockIdx.x * blockDim.x + threadIdx.x;  // 0 .. HW*4
    const int c = blockIdx.y, b = blockIdx.z;
    const int p = idx >> 2, j = idx & 3;
    const int g = __ldg(&groups[b*HW + p]);
    float4 v = ((const float4*)g_hard)[(b*NSEG + g)*4 + j];
    ((float4*)mask)[ (size_t)((b*CC + c)*HW + p)*4 + j ] = v;
}

// -------------------- launch --------------------
extern "C" void kernel_launch(void* const* d_in, const int* in_sizes, int n_in,
                              void* d_out, int out_size) {
    (void)in_sizes; (void)n_in; (void)out_size;
    const float* x      = (const float*)d_in[0];
    const int*   groups = (const int*)d_in[1];
    const float* Wc     = (const float*)d_in[2];
    const float* bc     = (const float*)d_in[3];
    float* out     = (float*)d_out;
    float* out_mask = out;
    float* out_gp   = out + OFF_GP;
    float* out_pp   = out + OFF_PP;
    float* out_sig  = out + OFF_SIG;

    void* sumsPtr = nullptr;
    cudaGetSymbolAddress(&sumsPtr, g_sums);
    cudaMemsetAsync(sumsPtr, 0, sizeof(float)*BB*NSEG*17);

    k_emb_sums<<<dim3(8, BB), 256>>>(x, groups, Wc, bc, out_pp);
    k_means<<<(BB*NSEG + 255)/256, 256>>>(out_gp);
    k_sigma<<<dim3(NSEG, BB), 256>>>(out_sig);

    const int chol_smem = LDA * 200 * sizeof(float);
    cudaFuncSetAttribute(k_chol, cudaFuncAttributeMaxDynamicSharedMemorySize, chol_smem);
    k_chol<<<BB, 512, chol_smem>>>(out_sig);

    // keys: key(42) = (0,42); foldlike split -> key_i = threefry(k, 0, i) (both words)
    uint32_t kg0, kg1, ku0, ku1;
    tf2x32(0u, 42u, 0u, 0u, kg0, kg1);
    tf2x32(0u, 42u, 0u, 1u, ku0, ku1);
    k_rng<<<(NTOT + 255)/256, 256>>>(kg0, kg1, ku0, ku1);

    k_logits<<<dim3(13, BB), 256>>>();
    k_mask<<<dim3(HW*4/256, CC, BB), 256>>>(groups, out_mask);
}